// round 16
// baseline (speedup 1.0000x reference)
#include <cuda_runtime.h>
#include <math.h>
#include <stdint.h>

#define BB    256
#define TT    1000
#define NIN   128
#define UNITS 512

#define CGS   8      // cluster size = column groups (64 cols each)
#define GRPS  16     // batch groups (clusters)
#define GBAT  16     // batches per group (warp = batch)
#define CCOLS 64     // cols per CTA

// dynamic smem layout
#define SW_BYTES   (UNITS * CCOLS * 4)               // 131072
#define OFF_MASK   SW_BYTES                          // u32 [2][16][16] = 2048
#define OFF_LIST   (OFF_MASK + 2048)                 // int [16][4][128] = 32768
#define OFF_CNT    (OFF_LIST + 32768)                // int [16][4] = 256
#define SMEM_TOTAL (OFF_CNT + 256)                   // 166144

// scratch
__device__ float g_iin[(size_t)BB * TT * UNITS];
__device__ float g_wrec[(size_t)UNITS * UNITS];

// ---------------------------------------------------------------------------
// Kernel A: GEMM (i_in = X @ W_in, bit-frozen serial ascending-k FMA chain)
// with W_rec diag-zero prep folded in as grid column 4.
// ---------------------------------------------------------------------------
#define GTM 128
#define GTN 128
#define GTK 32

__global__ __launch_bounds__(256) void gemm_prep_kernel(
    const float* __restrict__ X, const float* __restrict__ Wm,
    const float* __restrict__ W_rec)
{
    if (blockIdx.x == 4) {
        // prep: diag-zeroed W_rec copy (2000 blocks x 256 thr >= 262144 elems)
        int idx = blockIdx.y * 256 + threadIdx.x;
        if (idx < UNITS * UNITS) {
            int row = idx >> 9, col = idx & 511;
            g_wrec[idx] = (row == col) ? 0.0f : W_rec[idx];
        }
        return;
    }

    __shared__ float As[GTK][GTM + 4];
    __shared__ float Bs[GTK][GTN];
    const int bm = blockIdx.y * GTM;
    const int bn = blockIdx.x * GTN;
    const int tid = threadIdx.x;
    const int tx = tid & 15, ty = tid >> 4;

    float acc[8][8] = {};

    for (int kc = 0; kc < NIN; kc += GTK) {
        #pragma unroll
        for (int i = 0; i < 4; i++) {
            int idx = tid + i * 256;
            int m  = idx >> 3;
            int k4 = idx & 7;
            float4 vv = *(const float4*)(X + (size_t)(bm + m) * NIN + kc + k4 * 4);
            As[k4 * 4 + 0][m] = vv.x;
            As[k4 * 4 + 1][m] = vv.y;
            As[k4 * 4 + 2][m] = vv.z;
            As[k4 * 4 + 3][m] = vv.w;
        }
        #pragma unroll
        for (int i = 0; i < 4; i++) {
            int idx = tid + i * 256;
            int k  = idx >> 5;
            int n4 = idx & 31;
            *(float4*)(&Bs[k][n4 * 4]) =
                *(const float4*)(Wm + (size_t)(kc + k) * UNITS + bn + n4 * 4);
        }
        __syncthreads();

        #pragma unroll
        for (int k = 0; k < GTK; k++) {
            float a[8], b[8];
            *(float4*)(a)     = *(const float4*)(&As[k][ty * 8]);
            *(float4*)(a + 4) = *(const float4*)(&As[k][ty * 8 + 4]);
            *(float4*)(b)     = *(const float4*)(&Bs[k][tx * 8]);
            *(float4*)(b + 4) = *(const float4*)(&Bs[k][tx * 8 + 4]);
            #pragma unroll
            for (int i = 0; i < 8; i++)
                #pragma unroll
                for (int j = 0; j < 8; j++)
                    acc[i][j] = fmaf(a[i], b[j], acc[i][j]);
        }
        __syncthreads();
    }

    #pragma unroll
    for (int i = 0; i < 8; i++) {
        float* crow = g_iin + (size_t)(bm + ty * 8 + i) * UNITS + bn + tx * 8;
        __stcs((float4*)(crow),     *(float4*)(&acc[i][0]));
        __stcs((float4*)(crow + 4), *(float4*)(&acc[i][4]));
    }
}

// ---------------------------------------------------------------------------
// Kernel B: ALIF scan. Cluster of 8 CTAs = one batch-group (16 batches);
// CTA rank cg holds W_rec[:, cg*64..+64) in smem (128 KB). warp = batch,
// lane = column pair. Frozen arithmetic (verified bit-exact in R15):
// per-slice ascending (word, bit-in-byte) fadd chain, ((p0+p1)+p2)+p3,
// contracted step tree, Morton mask interleave.
// Mask exchange: DSMEM u64 stores to all 8 ranks + ONE cluster barrier/step.
// ---------------------------------------------------------------------------
__device__ __forceinline__ unsigned expand16(unsigned x) {
    x &= 0xFFFFu;
    x = (x | (x << 8)) & 0x00FF00FFu;
    x = (x | (x << 4)) & 0x0F0F0F0Fu;
    x = (x | (x << 2)) & 0x33333333u;
    x = (x | (x << 1)) & 0x55555555u;
    return x;
}

__device__ __forceinline__ uint32_t smem_u32(const void* p) {
    uint32_t a;
    asm("{ .reg .u64 t; cvta.to.shared.u64 t, %1; cvt.u32.u64 %0, t; }"
        : "=r"(a) : "l"(p));
    return a;
}

extern __shared__ char s_dyn[];

__global__ __launch_bounds__(512) __cluster_dims__(CGS, 1, 1)
void scan_kernel(float* __restrict__ out,
                 float decay, float omd, float decay_b, float omdb)
{
    float*    s_w    = (float*)s_dyn;                  // [512 rows][64 cols]
    unsigned* s_mask = (unsigned*)(s_dyn + OFF_MASK);  // [par][batch][word]
    int*      s_list = (int*)(s_dyn + OFF_LIST);       // [16][4][128]
    int*      s_cnt  = (int*)(s_dyn + OFF_CNT);        // [16][4]

    const int tid  = threadIdx.x;
    const int b    = tid >> 5;                 // warp = local batch
    const int lane = tid & 31;                 // column pair
    uint32_t rank;                             // = column group cg
    asm("mov.u32 %0, %%cluster_ctarank;" : "=r"(rank));
    const int grp = blockIdx.x >> 3;           // batch group
    const int B   = grp * GBAT + b;            // global batch

    // load W_rec[:, cg*64 .. +64) into smem (already diag-zeroed in g_wrec)
    {
        const float* src = g_wrec + rank * CCOLS;
        for (int i = tid; i < UNITS * (CCOLS / 4); i += 512) {
            int row = i >> 4, q = i & 15;
            *(float4*)(s_w + row * CCOLS + q * 4) =
                *(const float4*)(src + (size_t)row * UNITS + q * 4);
        }
    }
    __syncthreads();
    // everyone's smem exists/ready before any remote mask store
    asm volatile("barrier.cluster.arrive.aligned;" ::: "memory");
    asm volatile("barrier.cluster.wait.aligned;" ::: "memory");

    float v0 = 0.f, ba0 = 0.f, z0 = 0.f;
    float v1 = 0.f, ba1 = 0.f, z1 = 0.f;

    const char* wbase = (const char*)s_w + (lane << 3);     // + colpair*8B
    const float* iptr = g_iin + (size_t)B * TT * UNITS + rank * CCOLS + lane * 2;
    float*       optr = out   + (size_t)B * TT * UNITS + rank * CCOLS + lane * 2;
    int* listb = s_list + b * 4 * 128;
    const uint32_t maskbase = smem_u32(s_mask);

    for (int t = 0; t < TT; t++) {
        float2 inp = *(const float2*)(iptr + (size_t)t * UNITS);

        // masks for this step live in LOCAL smem (peers stored them last step)
        unsigned word = 0u;
        if (t > 0 && lane < 16)
            word = s_mask[(((t - 1) & 1) * 16 + b) * 16 + lane];

        // ---- compact 4 slice lists in frozen ascending (word,bit) order ----
        #pragma unroll
        for (int s = 0; s < 4; s++) {
            unsigned byte = (lane < 16) ? ((word >> (s * 8)) & 0xFFu) : 0u;
            int c  = __popc(byte);
            int sc = c;
            #pragma unroll
            for (int off = 1; off < 32; off <<= 1) {
                int nbr = __shfl_up_sync(0xffffffffu, sc, off);
                if (lane >= off) sc += nbr;
            }
            int pos = sc - c;
            unsigned mm = byte;
            int* dst = listb + s * 128;
            while (mm) {
                int j = __ffs(mm) - 1; mm &= mm - 1;
                dst[pos++] = (lane * 32 + s * 8 + j) << 8;   // row * 256 B
            }
            if (lane == 15) s_cnt[b * 4 + s] = sc;
        }
        __syncwarp();

        // ---- per-slice sums from smem weights, frozen order, unroll 8 ----
        float p0[4], p1[4];
        #pragma unroll
        for (int s = 0; s < 4; s++) {
            const int n = s_cnt[b * 4 + s];
            const int* il = listb + s * 128;
            float a0 = 0.f, a1 = 0.f;
            int i = 0;
            for (; i + 8 <= n; i += 8) {
                int4 ea = *(const int4*)(il + i);
                int4 eb = *(const int4*)(il + i + 4);
                float2 w0 = *(const float2*)(wbase + ea.x);
                float2 w1 = *(const float2*)(wbase + ea.y);
                float2 w2 = *(const float2*)(wbase + ea.z);
                float2 w3 = *(const float2*)(wbase + ea.w);
                float2 w4 = *(const float2*)(wbase + eb.x);
                float2 w5 = *(const float2*)(wbase + eb.y);
                float2 w6 = *(const float2*)(wbase + eb.z);
                float2 w7 = *(const float2*)(wbase + eb.w);
                a0 = __fadd_rn(a0, w0.x); a1 = __fadd_rn(a1, w0.y);
                a0 = __fadd_rn(a0, w1.x); a1 = __fadd_rn(a1, w1.y);
                a0 = __fadd_rn(a0, w2.x); a1 = __fadd_rn(a1, w2.y);
                a0 = __fadd_rn(a0, w3.x); a1 = __fadd_rn(a1, w3.y);
                a0 = __fadd_rn(a0, w4.x); a1 = __fadd_rn(a1, w4.y);
                a0 = __fadd_rn(a0, w5.x); a1 = __fadd_rn(a1, w5.y);
                a0 = __fadd_rn(a0, w6.x); a1 = __fadd_rn(a1, w6.y);
                a0 = __fadd_rn(a0, w7.x); a1 = __fadd_rn(a1, w7.y);
            }
            if (i + 4 <= n) {
                int4 ea = *(const int4*)(il + i);
                float2 w0 = *(const float2*)(wbase + ea.x);
                float2 w1 = *(const float2*)(wbase + ea.y);
                float2 w2 = *(const float2*)(wbase + ea.z);
                float2 w3 = *(const float2*)(wbase + ea.w);
                a0 = __fadd_rn(a0, w0.x); a1 = __fadd_rn(a1, w0.y);
                a0 = __fadd_rn(a0, w1.x); a1 = __fadd_rn(a1, w1.y);
                a0 = __fadd_rn(a0, w2.x); a1 = __fadd_rn(a1, w2.y);
                a0 = __fadd_rn(a0, w3.x); a1 = __fadd_rn(a1, w3.y);
                i += 4;
            }
            for (; i < n; i++) {
                float2 w = *(const float2*)(wbase + il[i]);
                a0 = __fadd_rn(a0, w.x); a1 = __fadd_rn(a1, w.y);
            }
            p0[s] = a0; p1[s] = a1;
        }
        float rec0 = __fadd_rn(__fadd_rn(__fadd_rn(p0[0], p0[1]), p0[2]), p0[3]);
        float rec1 = __fadd_rn(__fadd_rn(__fadd_rn(p1[0], p1[1]), p1[2]), p1[3]);

        // ---- frozen contracted step tree (both cols) ----
        float nb0  = fmaf(decay_b, ba0, __fmul_rn(omdb, z0));
        float thr0 = fmaf(nb0, 1.6f, 0.01f);
        float it0  = __fadd_rn(inp.x, rec0);
        float nv0  = fmaf(-z0, thr0, fmaf(decay, v0, __fmul_rn(omd, it0)));
        float zn0  = (nv0 > thr0) ? 1.0f : 0.0f;

        float nb1  = fmaf(decay_b, ba1, __fmul_rn(omdb, z1));
        float thr1 = fmaf(nb1, 1.6f, 0.01f);
        float it1  = __fadd_rn(inp.y, rec1);
        float nv1  = fmaf(-z1, thr1, fmaf(decay, v1, __fmul_rn(omd, it1)));
        float zn1  = (nv1 > thr1) ? 1.0f : 0.0f;

        v0 = nv0; ba0 = nb0; z0 = zn0;
        v1 = nv1; ba1 = nb1; z1 = zn1;
        {
            float2 zz = make_float2(zn0, zn1);
            __stcs((float2*)(optr + (size_t)t * UNITS), zz);
        }

        // ---- publish this CTA's 2 Morton-interleaved mask words for batch b
        //      to ALL 8 cluster ranks (including self) via DSMEM u64 store ----
        unsigned bal0 = __ballot_sync(0xffffffffu, zn0 != 0.f);
        unsigned bal1 = __ballot_sync(0xffffffffu, zn1 != 0.f);
        unsigned w0 = expand16(bal0)       | (expand16(bal1) << 1);
        unsigned w1 = expand16(bal0 >> 16) | (expand16(bal1 >> 16) << 1);
        if (lane < 8) {
            unsigned long long val =
                (unsigned long long)w0 | ((unsigned long long)w1 << 32);
            uint32_t laddr = maskbase +
                (((unsigned)(t & 1) * 16 + b) * 16 + rank * 2) * 4;
            uint32_t raddr;
            asm("mapa.shared::cluster.u32 %0, %1, %2;"
                : "=r"(raddr) : "r"(laddr), "r"((uint32_t)lane));
            asm volatile("st.shared::cluster.u64 [%0], %1;"
                         :: "r"(raddr), "l"(val) : "memory");
        }

        // one cluster barrier per step: orders DSMEM stores, gates buffers
        asm volatile("barrier.cluster.arrive.aligned;" ::: "memory");
        asm volatile("barrier.cluster.wait.aligned;" ::: "memory");
    }
}

// ---------------------------------------------------------------------------
extern "C" void kernel_launch(void* const* d_in, const int* in_sizes, int n_in,
                              void* d_out, int out_size) {
    const float* x     = (const float*)d_in[0];   // [B, T, N_IN]
    const float* W_in  = (const float*)d_in[1];   // [N_IN, UNITS]
    const float* W_rec = (const float*)d_in[2];   // [UNITS, UNITS]
    float* out = (float*)d_out;                   // [B, T, UNITS]

    (void)in_sizes; (void)n_in; (void)out_size;

    // frozen correctly-rounded fp32 constants
    float decay   = (float)exp(-1.0 / 20.0);
    float decay_b = (float)exp(-1.0 / 200.0);
    float omd     = 1.0f - decay;
    float omdb    = 1.0f - decay_b;

    cudaFuncSetAttribute(scan_kernel,
                         cudaFuncAttributeMaxDynamicSharedMemorySize, SMEM_TOTAL);

    dim3 ggrid(5, (BB * TT) / GTM);               // cols 0..3 gemm, col 4 prep
    gemm_prep_kernel<<<ggrid, 256>>>(x, W_in, W_rec);

    scan_kernel<<<CGS * GRPS, 512, SMEM_TOTAL>>>(out, decay, omd, decay_b, omdb);
}